// round 13
// baseline (speedup 1.0000x reference)
#include <cuda_runtime.h>
#include <cuda_bf16.h>

#define FWSZ 524288u
#define QKS  262144u
typedef unsigned long long ull;
typedef __nv_bfloat16 bf16;

static __device__ __forceinline__ ull pack2(float lo, float hi){
  ull r; asm("mov.b64 %0,{%1,%2};" : "=l"(r) : "f"(lo), "f"(hi)); return r;
}
static __device__ __forceinline__ void fma2(ull &d, ull a, ull b){
  asm("fma.rn.f32x2 %0,%1,%2,%0;" : "+l"(d) : "l"(a), "l"(b));
}
static __device__ __forceinline__ float2 unpack2(ull v){
  float2 f; asm("mov.b64 {%0,%1},%2;" : "=f"(f.x), "=f"(f.y) : "l"(v)); return f;
}
static __device__ __forceinline__ void mma16816(float* c, const unsigned* a, const unsigned* b){
  asm volatile("mma.sync.aligned.m16n8k16.row.col.f32.bf16.bf16.f32 "
    "{%0,%1,%2,%3},{%4,%5,%6,%7},{%8,%9},{%0,%1,%2,%3};"
    : "+f"(c[0]),"+f"(c[1]),"+f"(c[2]),"+f"(c[3])
    : "r"(a[0]),"r"(a[1]),"r"(a[2]),"r"(a[3]), "r"(b[0]),"r"(b[1]));
}
static __device__ __forceinline__ void split2(float v0, float v1, unsigned &hi, unsigned &lo){
  bf16 h0 = __float2bfloat16(v0), h1 = __float2bfloat16(v1);
  bf16 l0 = __float2bfloat16(v0 - __bfloat162float(h0));
  bf16 l1 = __float2bfloat16(v1 - __bfloat162float(h1));
  __nv_bfloat162 hh; hh.x = h0; hh.y = h1;
  __nv_bfloat162 ll; ll.x = l0; ll.y = l1;
  hi = *(unsigned*)&hh; lo = *(unsigned*)&ll;
}
static __device__ __forceinline__ void cpa16(unsigned s, const void* g){
  asm volatile("cp.async.cg.shared.global [%0], [%1], 16;\n" :: "r"(s), "l"(g));
}
static __device__ __forceinline__ void cpcommit(){ asm volatile("cp.async.commit_group;\n" ::: "memory"); }
static __device__ __forceinline__ void cpwait0(){ asm volatile("cp.async.wait_group 0;\n" ::: "memory"); }
static __device__ __forceinline__ void cpwait1(){ asm volatile("cp.async.wait_group 1;\n" ::: "memory"); }
static __device__ __forceinline__ unsigned s2u(const void* p){
  return (unsigned)__cvta_generic_to_shared(p);
}

// planes (float units): Qh 0..3, Ql 4..7, Kh 8..11, Kl 12..15 (PAIRED layout), Vh 16..19, Vl 20..23,
// A 24..31, H 32..55, T 56..87; tail MS/PM/PS
__device__ float g_scratch[88u*FWSZ + 300000u];

// ---------------- LN stats over F per (c,w); optional copy-through to cp ----------------
__global__ __launch_bounds__(256) void k_stats(const float* __restrict__ in, float2* __restrict__ ms,
                                               float* __restrict__ cp){
  int c = blockIdx.y, lane = threadIdx.x & 31, fg = threadIdx.x >> 5;
  int w = blockIdx.x*32 + lane;
  const float* base = in + (size_t)c*FWSZ + w;
  float* cpb = cp ? (cp + (size_t)c*FWSZ + w) : nullptr;
  float s = 0.f, s2 = 0.f;
  for (int f = fg; f < 1024; f += 8){
    float v = base[(size_t)f*512u];
    if (cpb) cpb[(size_t)f*512u] = v;
    s += v; s2 += v*v;
  }
  __shared__ float sh[2][8][32];
  sh[0][fg][lane] = s; sh[1][fg][lane] = s2;
  __syncthreads();
  if (fg == 0){
    float S = 0.f, S2 = 0.f;
    #pragma unroll
    for (int r = 0; r < 8; r++){ S += sh[0][r][lane]; S2 += sh[1][r][lane]; }
    float mu  = S*(1.f/1024.f);
    float var = S2*(1.f/1024.f) - mu*mu;
    ms[c*512 + w] = make_float2(mu, rsqrtf(var + 1e-8f));
  }
}

// ---------------- fused (optional-LN) 1x3 conv; NS split-bf16 outputs (+PMASK paired layout) + NP fp32 ----------------
template<int IC, int NS, int NP, bool LN, int PMASK>
__global__ __launch_bounds__(256) void k_lnconv(const float* __restrict__ in, const float2* __restrict__ ms,
    const float* __restrict__ g, const float* __restrict__ b,
    const float* __restrict__ w0, const float* __restrict__ w1, const float* __restrict__ w2,
    bf16* __restrict__ h0, bf16* __restrict__ l0, bf16* __restrict__ h1, bf16* __restrict__ l1,
    bf16* __restrict__ h2, bf16* __restrict__ l2, float* __restrict__ p0)
{
  const int NO = NS + NP;
  __shared__ ull ws[NO*4*IC*3];
  for (int i = threadIdx.x; i < NO*4*IC*3; i += 256){
    int s = i/(4*IC*3), r = i - s*(4*IC*3);
    const float* wsrc = (s==0)? w0 : (s==1)? w1 : w2;
    int p = r/(IC*3), rr = r - p*(IC*3);
    ws[i] = pack2(wsrc[(2*p)*IC*3 + rr], wsrc[(2*p+1)*IC*3 + rr]);
  }
  __syncthreads();
  unsigned t = blockIdx.x*256u + threadIdx.x;
  unsigned base = t*2u;
  int w = base & 511u, f = base >> 9;
  bool w0v = (w > 0), w3v = (w < 510);
  ull acc[NO*4][2];
  #pragma unroll
  for (int p = 0; p < NO*4; p++){ acc[p][0] = 0ull; acc[p][1] = 0ull; }
  #pragma unroll
  for (int ic = 0; ic < IC; ic++){
    const float* ip = in + (size_t)ic*FWSZ + base;
    float v0 = w0v ? ip[-1] : 0.f, v1 = ip[0], v2 = ip[1], v3 = w3v ? ip[2] : 0.f;
    float n0, n1, n2, n3;
    if (LN){
      float gf = g[ic*1024 + f], bf = b[ic*1024 + f];
      const float2* msc = ms + ic*512;
      if (w0v){ float2 m = msc[w-1]; float sc = m.y*gf; n0 = v0*sc + (bf - m.x*sc); } else n0 = 0.f;
      { float2 m = msc[w];   float sc = m.y*gf; n1 = v1*sc + (bf - m.x*sc); }
      { float2 m = msc[w+1]; float sc = m.y*gf; n2 = v2*sc + (bf - m.x*sc); }
      if (w3v){ float2 m = msc[w+2]; float sc = m.y*gf; n3 = v3*sc + (bf - m.x*sc); } else n3 = 0.f;
    } else { n0 = v0; n1 = v1; n2 = v2; n3 = v3; }
    ull b0 = pack2(n0,n0), b1 = pack2(n1,n1), b2 = pack2(n2,n2), b3 = pack2(n3,n3);
    #pragma unroll
    for (int p = 0; p < NO*4; p++){
      const ull* wp = &ws[(p*IC + ic)*3];
      ull q0 = wp[0], q1 = wp[1], q2 = wp[2];
      fma2(acc[p][0], b0, q0); fma2(acc[p][0], b1, q1); fma2(acc[p][0], b2, q2);
      fma2(acc[p][1], b1, q0); fma2(acc[p][1], b2, q1); fma2(acc[p][1], b3, q2);
    }
  }
  int h = f >> 7, dd = f & 127;
  #pragma unroll
  for (int s = 0; s < NS; s++){
    bf16* hp = (s==0)? h0 : (s==1)? h1 : h2;
    bf16* lp = (s==0)? l0 : (s==1)? l1 : l2;
    #pragma unroll
    for (int p = 0; p < 4; p++){
      float2 a = unpack2(acc[s*4+p][0]), c = unpack2(acc[s*4+p][1]);
      if ((PMASK >> s) & 1){
        // paired layout: (dd,w) at (dd>>1)*1024 + 2w + (dd&1)
        #pragma unroll
        for (int q = 0; q < 2; q++){
          int oc = 2*p + q;
          float u0 = q ? a.y : a.x, u1 = q ? c.y : c.x;
          bf16 H0 = __float2bfloat16(u0); bf16 L0 = __float2bfloat16(u0 - __bfloat162float(H0));
          bf16 H1 = __float2bfloat16(u1); bf16 L1 = __float2bfloat16(u1 - __bfloat162float(H1));
          size_t ib = (size_t)(oc*8 + h)*65536u + (size_t)(dd>>1)*1024u + (unsigned)(dd&1) + 2u*(unsigned)w;
          hp[ib] = H0; hp[ib + 2] = H1;
          lp[ib] = L0; lp[ib + 2] = L1;
        }
      } else {
        unsigned hh, ll;
        split2(a.x, c.x, hh, ll);
        *(unsigned*)(hp + (size_t)(2*p)*FWSZ + base) = hh;
        *(unsigned*)(lp + (size_t)(2*p)*FWSZ + base) = ll;
        split2(a.y, c.y, hh, ll);
        *(unsigned*)(hp + (size_t)(2*p+1)*FWSZ + base) = hh;
        *(unsigned*)(lp + (size_t)(2*p+1)*FWSZ + base) = ll;
      }
    }
  }
  if (NP){
    #pragma unroll
    for (int p = 0; p < 4; p++){
      float2 a = unpack2(acc[NS*4+p][0]), c = unpack2(acc[NS*4+p][1]);
      p0[(size_t)(2*p)*FWSZ   + base]     = a.x;
      p0[(size_t)(2*p)*FWSZ   + base + 1] = c.x;
      p0[(size_t)(2*p+1)*FWSZ + base]     = a.y;
      p0[(size_t)(2*p+1)*FWSZ + base + 1] = c.y;
    }
  }
}

// ---------------- QK^T split-bf16 mma, cp.async double-buffered, PAIRED operand layout ----------------
// Qh/Ql/Kh/Kl planes: [z][dd2(64)][w(512)][2] bf16. grid (4 kw,4 qw,64 z), 256 thr.
#define QK_TILE 4352            // 16 rows * 272 bf16 per tensor per buffer
#define QK_SMEM (2*4*QK_TILE*2) // 69632 bytes
__global__ __launch_bounds__(256,2) void k_gemm_qk_mma(
    const bf16* __restrict__ Qh, const bf16* __restrict__ Ql,
    const bf16* __restrict__ Kh, const bf16* __restrict__ Kl,
    const float* __restrict__ b1p, const float* __restrict__ b2p, const float* __restrict__ b3p,
    float* __restrict__ o, float* __restrict__ pmax, float* __restrict__ psum)
{
  extern __shared__ bf16 dynqk[];
  __shared__ float red[512];
  __shared__ float mrow[128];
  int z = blockIdx.z, qw0 = blockIdx.y*128, kw0 = blockIdx.x*128, bx = blockIdx.x;
  int tid = threadIdx.x, lane = tid & 31, wid = tid >> 5;
  int wy = wid >> 2, wx = wid & 3;
  int m0 = wy*64, n0 = wx*32;
  int g = lane >> 2, t4 = lane & 3;
  const bf16* bQh = Qh + (size_t)z*65536u + 2u*qw0;
  const bf16* bQl = Ql + (size_t)z*65536u + 2u*qw0;
  const bf16* bKh = Kh + (size_t)z*65536u + 2u*kw0;
  const bf16* bKl = Kl + (size_t)z*65536u + 2u*kw0;

  auto fill = [&](int kb, int buf){
    int d20 = kb*16;
    bf16* sb = dynqk + buf*(4*QK_TILE);
    #pragma unroll
    for (int it = 0; it < 8; it++){
      int c = it*256 + tid;
      int tt = c >> 9, rem = c & 511, row = rem >> 5, ch = rem & 31;
      const bf16* gp = ((tt==0)?bQh:(tt==1)?bQl:(tt==2)?bKh:bKl)
                       + (size_t)(d20+row)*1024u + ch*8;
      cpa16(s2u(sb + tt*QK_TILE + row*272 + ch*8), gp);
    }
    cpcommit();
  };

  float acc[4][4][4];
  #pragma unroll
  for (int mt = 0; mt < 4; mt++)
    #pragma unroll
    for (int nt = 0; nt < 4; nt++)
      #pragma unroll
      for (int i = 0; i < 4; i++) acc[mt][nt][i] = 0.f;

  fill(0, 0);
  for (int kb = 0; kb < 4; kb++){
    if (kb < 3){ fill(kb+1, (kb+1)&1); cpwait1(); } else cpwait0();
    __syncthreads();
    const unsigned* wT  = (const unsigned*)(dynqk + (kb&1)*(4*QK_TILE));
    const unsigned* wQh = wT;
    const unsigned* wQl = wT + 2176;
    const unsigned* wKh = wT + 4352;
    const unsigned* wKl = wT + 6528;
    #pragma unroll
    for (int ks = 0; ks < 2; ks++){
      int rb0 = (ks*8 + t4)*136, rb4 = rb0 + 4*136;
      unsigned bh[4][2], bl[4][2];
      #pragma unroll
      for (int nt = 0; nt < 4; nt++){
        int n = n0 + nt*8 + g;
        bh[nt][0] = wKh[rb0 + n]; bh[nt][1] = wKh[rb4 + n];
        bl[nt][0] = wKl[rb0 + n]; bl[nt][1] = wKl[rb4 + n];
      }
      #pragma unroll
      for (int mt = 0; mt < 4; mt++){
        int m = m0 + mt*16 + g;
        unsigned ah[4], al[4];
        ah[0] = wQh[rb0 + m]; ah[1] = wQh[rb0 + m + 8];
        ah[2] = wQh[rb4 + m]; ah[3] = wQh[rb4 + m + 8];
        al[0] = wQl[rb0 + m]; al[1] = wQl[rb0 + m + 8];
        al[2] = wQl[rb4 + m]; al[3] = wQl[rb4 + m + 8];
        #pragma unroll
        for (int nt = 0; nt < 4; nt++){
          mma16816(acc[mt][nt], ah, bh[nt]);
          mma16816(acc[mt][nt], ah, bl[nt]);
          mma16816(acc[mt][nt], al, bh[nt]);
        }
      }
    }
    __syncthreads();
  }

  const float sc = 0.08838834764831845f;   // 1/sqrt(128)
  #pragma unroll
  for (int mt = 0; mt < 4; mt++){
    #pragma unroll
    for (int half = 0; half < 2; half++){
      int lrow = m0 + mt*16 + g + half*8;
      size_t rowb = (size_t)z*QKS + (size_t)(qw0 + lrow)*512u;
      #pragma unroll
      for (int nt = 0; nt < 4; nt++){
        size_t ix = rowb + kw0 + n0 + nt*8 + 2*t4;
        float v0 = acc[mt][nt][half*2+0]*sc, v1 = acc[mt][nt][half*2+1]*sc;
        float2 c1 = *(const float2*)(b1p + ix), c2 = *(const float2*)(b2p + ix);
        v0 += c1.x + c2.x; v1 += c1.y + c2.y;
        if (b3p){ float2 c3 = *(const float2*)(b3p + ix); v0 += c3.x; v1 += c3.y; }
        *(float2*)(o + ix) = make_float2(v0, v1);
        acc[mt][nt][half*2+0] = v0; acc[mt][nt][half*2+1] = v1;
      }
    }
  }
  #pragma unroll
  for (int mt = 0; mt < 4; mt++){
    #pragma unroll
    for (int half = 0; half < 2; half++){
      float m = -3.4e38f;
      #pragma unroll
      for (int nt = 0; nt < 4; nt++){
        m = fmaxf(m, acc[mt][nt][half*2+0]); m = fmaxf(m, acc[mt][nt][half*2+1]);
      }
      m = fmaxf(m, __shfl_xor_sync(0xffffffffu, m, 1));
      m = fmaxf(m, __shfl_xor_sync(0xffffffffu, m, 2));
      int lrow = m0 + mt*16 + g + half*8;
      if (t4 == 0) red[lrow*4 + wx] = m;
    }
  }
  __syncthreads();
  if (tid < 128)
    mrow[tid] = fmaxf(fmaxf(red[tid*4], red[tid*4+1]), fmaxf(red[tid*4+2], red[tid*4+3]));
  __syncthreads();
  #pragma unroll
  for (int mt = 0; mt < 4; mt++){
    #pragma unroll
    for (int half = 0; half < 2; half++){
      int lrow = m0 + mt*16 + g + half*8;
      float M = mrow[lrow];
      float s = 0.f;
      #pragma unroll
      for (int nt = 0; nt < 4; nt++)
        s += __expf(acc[mt][nt][half*2+0] - M) + __expf(acc[mt][nt][half*2+1] - M);
      s += __shfl_xor_sync(0xffffffffu, s, 1);
      s += __shfl_xor_sync(0xffffffffu, s, 2);
      if (t4 == 0) red[lrow*4 + wx] = s;
    }
  }
  __syncthreads();
  if (tid < 128){
    float S = red[tid*4] + red[tid*4+1] + red[tid*4+2] + red[tid*4+3];
    size_t pi = ((size_t)z*512u + qw0 + tid)*4u + bx;
    pmax[pi] = mrow[tid]; psum[pi] = S;
  }
}

// ---------------- AV split-bf16 mma, cp.async double-buffered, fused softmax ----------------
// Vh/Vl planes [z][dd][kw] bf16 (old layout); P fp32 [z][qw][kw]. grid (4,1,64), 256 thr.
#define AV_VT 10240    // 128*40 bf16 bytes
#define AV_PT 18432    // 128*36 fp32 bytes
#define AV_BUF (2*AV_VT + AV_PT)   // 38912
#define AV_SMEM (2*AV_BUF)         // 77824
__global__ __launch_bounds__(256,2) void k_gemm_av_mma(
    const bf16* __restrict__ Vh, const bf16* __restrict__ Vl, const float* __restrict__ pq,
    const float* __restrict__ pmax, const float* __restrict__ psum, float* __restrict__ A)
{
  extern __shared__ char dynav[];
  __shared__ float mxs[128], ivs[128];
  int z = blockIdx.z, qw0 = blockIdx.x*128;
  int tid = threadIdx.x, lane = tid & 31, wid = tid >> 5;
  int wy = wid >> 2, wx = wid & 3;
  int m0 = wy*64, n0 = wx*32;
  int g = lane >> 2, t4 = lane & 3;
  const bf16* bVh = Vh + (size_t)z*65536u;
  const bf16* bVl = Vl + (size_t)z*65536u;
  const float* bP = pq + (size_t)z*QKS;
  if (tid < 128){
    size_t pi = ((size_t)z*512u + qw0 + tid)*4u;
    float m0v = pmax[pi], m1 = pmax[pi+1], m2 = pmax[pi+2], m3 = pmax[pi+3];
    float m = fmaxf(fmaxf(m0v,m1), fmaxf(m2,m3));
    float s = psum[pi]*__expf(m0v-m) + psum[pi+1]*__expf(m1-m)
            + psum[pi+2]*__expf(m2-m) + psum[pi+3]*__expf(m3-m);
    mxs[tid] = m; ivs[tid] = 1.f/s;
  }

  auto fill = [&](int kc, int buf){
    int k0 = kc*32;
    char* base = dynav + buf*AV_BUF;
    #pragma unroll
    for (int it = 0; it < 8; it++){
      int c = it*256 + tid;
      if (c < 1024){
        int tt = c >> 9, rem = c & 511, row = rem >> 2, col = rem & 3;
        const bf16* gp = (tt ? bVl : bVh) + (size_t)row*512u + k0 + col*8;
        cpa16(s2u(base + tt*AV_VT + (row*40 + col*8)*2), gp);
      } else {
        int rem = c - 1024, row = rem >> 3, col = rem & 7;
        const float* gp = bP + (size_t)(qw0+row)*512u + k0 + col*4;
        cpa16(s2u(base + 2*AV_VT + (row*36 + col*4)*4), gp);
      }
    }
    cpcommit();
  };

  float acc[4][4][4];
  #pragma unroll
  for (int mt = 0; mt < 4; mt++)
    #pragma unroll
    for (int nt = 0; nt < 4; nt++)
      #pragma unroll
      for (int i = 0; i < 4; i++) acc[mt][nt][i] = 0.f;

  fill(0, 0);
  for (int kc = 0; kc < 16; kc++){
    if (kc < 15){ fill(kc+1, (kc+1)&1); cpwait1(); } else cpwait0();
    __syncthreads();
    char* cb = dynav + (kc&1)*AV_BUF;
    const bf16* sVh_ = (const bf16*)cb;
    const bf16* sVl_ = (const bf16*)(cb + AV_VT);
    const float* sP_ = (const float*)(cb + 2*AV_VT);
    #pragma unroll
    for (int ks = 0; ks < 2; ks++){
      int kk = ks*16 + 2*t4;
      unsigned bh[4][2], bl[4][2];
      #pragma unroll
      for (int nt = 0; nt < 4; nt++){
        int row = n0 + nt*8 + g;
        float mrw = mxs[row];
        const float* pb = sP_ + row*36 + kk;
        float2 v0 = *(const float2*)pb;
        float2 v1 = *(const float2*)(pb + 8);
        split2(__expf(v0.x-mrw), __expf(v0.y-mrw), bh[nt][0], bl[nt][0]);
        split2(__expf(v1.x-mrw), __expf(v1.y-mrw), bh[nt][1], bl[nt][1]);
      }
      #pragma unroll
      for (int mt = 0; mt < 4; mt++){
        int row = m0 + mt*16 + g;
        unsigned ah[4], al[4];
        ah[0] = *(const unsigned*)(sVh_ + row*40 + kk);
        ah[1] = *(const unsigned*)(sVh_ + (row+8)*40 + kk);
        ah[2] = *(const unsigned*)(sVh_ + row*40 + kk+8);
        ah[3] = *(const unsigned*)(sVh_ + (row+8)*40 + kk+8);
        al[0] = *(const unsigned*)(sVl_ + row*40 + kk);
        al[1] = *(const unsigned*)(sVl_ + (row+8)*40 + kk);
        al[2] = *(const unsigned*)(sVl_ + row*40 + kk+8);
        al[3] = *(const unsigned*)(sVl_ + (row+8)*40 + kk+8);
        #pragma unroll
        for (int nt = 0; nt < 4; nt++){
          mma16816(acc[mt][nt], ah, bh[nt]);
          mma16816(acc[mt][nt], ah, bl[nt]);
          mma16816(acc[mt][nt], al, bh[nt]);
        }
      }
    }
    __syncthreads();
  }
  #pragma unroll
  for (int mt = 0; mt < 4; mt++){
    #pragma unroll
    for (int half = 0; half < 2; half++){
      int row = m0 + mt*16 + g + half*8;
      size_t rowb = (size_t)z*65536u + (size_t)row*512u + qw0;
      #pragma unroll
      for (int nt = 0; nt < 4; nt++){
        int col = n0 + nt*8 + 2*t4;
        float iv0 = ivs[col], iv1 = ivs[col+1];
        *(float2*)(A + rowb + col) =
            make_float2(acc[mt][nt][half*2+0]*iv0, acc[mt][nt][half*2+1]*iv1);
      }
    }
  }
}

// ---------------- 3x3 conv with fused LN (24ch -> 32ch), SquaredReLU ----------------
__global__ __launch_bounds__(256) void k_c3ln(const float* __restrict__ in, const float2* __restrict__ ms,
    const float* __restrict__ g, const float* __restrict__ b, const float* __restrict__ wgt,
    float* __restrict__ o)
{
  __shared__ ull ws[16*24*9];
  for (int i = threadIdx.x; i < 16*24*9; i += 256){
    int p = i/216, r = i - p*216;
    ws[i] = pack2(wgt[(2*p)*216 + r], wgt[(2*p+1)*216 + r]);
  }
  __syncthreads();
  unsigned t = blockIdx.x*256u + threadIdx.x;
  unsigned base = t*2u;
  int w = base & 511u, f = base >> 9;
  bool r0v = (f > 0), r2v = (f < 1023), w0v = (w > 0), w3v = (w < 510);
  ull acc[16][2];
  #pragma unroll
  for (int p = 0; p < 16; p++){ acc[p][0] = 0ull; acc[p][1] = 0ull; }
  #pragma unroll 2
  for (int ic = 0; ic < 24; ic++){
    const float* ip = in + (size_t)ic*FWSZ + base;
    const float2* msc = ms + ic*512;
    float gm1 = r0v ? g[ic*1024+f-1] : 0.f, bm1 = r0v ? b[ic*1024+f-1] : 0.f;
    float gc  = g[ic*1024+f],               bc  = b[ic*1024+f];
    float gp1 = r2v ? g[ic*1024+f+1] : 0.f, bp1 = r2v ? b[ic*1024+f+1] : 0.f;
    float2 m0 = w0v ? msc[w-1] : make_float2(0.f,1.f);
    float2 m1 = msc[w], m2 = msc[w+1];
    float2 m3 = w3v ? msc[w+2] : make_float2(0.f,1.f);
    float u[3][4];
    {
      const float* rp = ip - 512;
      u[0][0] = (r0v&&w0v)? rp[-1]:0.f; u[0][1] = r0v? rp[0]:0.f; u[0][2] = r0v? rp[1]:0.f; u[0][3] = (r0v&&w3v)? rp[2]:0.f;
      u[1][0] = w0v? ip[-1]:0.f;        u[1][1] = ip[0];          u[1][2] = ip[1];          u[1][3] = w3v? ip[2]:0.f;
      const float* rq = ip + 512;
      u[2][0] = (r2v&&w0v)? rq[-1]:0.f; u[2][1] = r2v? rq[0]:0.f; u[2][2] = r2v? rq[1]:0.f; u[2][3] = (r2v&&w3v)? rq[2]:0.f;
    }
    auto nrm = [] (float v, float2 m, float gg, float bb, bool valid)->float{
      float sc = m.y*gg; return valid ? (v*sc + (bb - m.x*sc)) : 0.f; };
    u[0][0] = nrm(u[0][0], m0, gm1, bm1, r0v&&w0v);
    u[0][1] = nrm(u[0][1], m1, gm1, bm1, r0v);
    u[0][2] = nrm(u[0][2], m2, gm1, bm1, r0v);
    u[0][3] = nrm(u[0][3], m3, gm1, bm1, r0v&&w3v);
    u[1][0] = nrm(u[1][0], m0, gc,  bc,  w0v);
    u[1][1] = nrm(u[1][1], m1, gc,  bc,  true);
    u[1][2] = nrm(u[1][2], m2, gc,  bc,  true);
    u[1][3] = nrm(u[1][3], m3, gc,  bc,  w3v);
    u[2][0] = nrm(u[2][0], m0, gp1, bp1, r2v&&w0v);
    u[2][1] = nrm(u[2][1], m1, gp1, bp1, r2v);
    u[2][2] = nrm(u[2][2], m2, gp1, bp1, r2v);
    u[2][3] = nrm(u[2][3], m3, gp1, bp1, r2v&&w3v);
    #pragma unroll
    for (int k = 0; k < 9; k++){
      int ky = k/3, kx = k - ky*3;
      ull b0 = pack2(u[ky][kx],   u[ky][kx]);
      ull b1 = pack2(u[ky][kx+1], u[ky][kx+1]);
      #pragma unroll
      for (int p = 0; p < 16; p++){
        ull wv = ws[(p*24 + ic)*9 + k];
        fma2(acc[p][0], b0, wv); fma2(acc[p][1], b1, wv);
      }
    }
  }
  #pragma unroll
  for (int p = 0; p < 16; p++){
    float2 a = unpack2(acc[p][0]), bv = unpack2(acc[p][1]);
    float o00 = fmaxf(a.x, 0.f);  o00 *= o00;
    float o10 = fmaxf(a.y, 0.f);  o10 *= o10;
    float o01 = fmaxf(bv.x, 0.f); o01 *= o01;
    float o11 = fmaxf(bv.y, 0.f); o11 *= o11;
    o[(size_t)(2*p)*FWSZ   + base]     = o00;
    o[(size_t)(2*p)*FWSZ   + base + 1] = o01;
    o[(size_t)(2*p+1)*FWSZ + base]     = o10;
    o[(size_t)(2*p+1)*FWSZ + base + 1] = o11;
  }
}

// ---------------- plain 3x3 conv (32ch -> 8ch) + residual add ----------------
__global__ __launch_bounds__(256) void k_c3b(const float* __restrict__ in, const float* __restrict__ wgt,
    const float* __restrict__ addsrc, float* __restrict__ o)
{
  __shared__ ull ws[4*32*9];
  for (int i = threadIdx.x; i < 4*32*9; i += 256){
    int p = i/288, r = i - p*288;
    ws[i] = pack2(wgt[(2*p)*288 + r], wgt[(2*p+1)*288 + r]);
  }
  __syncthreads();
  unsigned t = blockIdx.x*256u + threadIdx.x;
  unsigned base = t*2u;
  int w = base & 511u, f = base >> 9;
  bool r0v = (f > 0), r2v = (f < 1023), w0v = (w > 0), w3v = (w < 510);
  ull acc[4][2];
  #pragma unroll
  for (int p = 0; p < 4; p++){ acc[p][0] = 0ull; acc[p][1] = 0ull; }
  #pragma unroll 4
  for (int ic = 0; ic < 32; ic++){
    const float* ip = in + (size_t)ic*FWSZ + base;
    float u[3][4];
    {
      const float* rp = ip - 512;
      u[0][0] = (r0v&&w0v)? rp[-1]:0.f; u[0][1] = r0v? rp[0]:0.f; u[0][2] = r0v? rp[1]:0.f; u[0][3] = (r0v&&w3v)? rp[2]:0.f;
      u[1][0] = w0v? ip[-1]:0.f;        u[1][1] = ip[0];          u[1][2] = ip[1];          u[1][3] = w3v? ip[2]:0.f;
      const float* rq = ip + 512;
      u[2][0] = (r2v&&w0v)? rq[-1]:0.f; u[2][1] = r2v? rq[0]:0.f; u[2][2] = r2v? rq[1]:0.f; u[2][3] = (r2v&&w3v)? rq[2]:0.f;
    }
    #pragma unroll
    for (int k = 0; k < 9; k++){
      int ky = k/3, kx = k - ky*3;
      ull b0 = pack2(u[ky][kx],   u[ky][kx]);
      ull b1 = pack2(u[ky][kx+1], u[ky][kx+1]);
      #pragma unroll
      for (int p = 0; p < 4; p++){
        ull wv = ws[(p*32 + ic)*9 + k];
        fma2(acc[p][0], b0, wv); fma2(acc[p][1], b1, wv);
      }
    }
  }
  #pragma unroll
  for (int p = 0; p < 4; p++){
    float2 a = unpack2(acc[p][0]), bv = unpack2(acc[p][1]);
    o[(size_t)(2*p)*FWSZ   + base]     = a.x  + addsrc[(size_t)(2*p)*FWSZ + base];
    o[(size_t)(2*p)*FWSZ   + base + 1] = bv.x + addsrc[(size_t)(2*p)*FWSZ + base + 1];
    o[(size_t)(2*p+1)*FWSZ + base]     = a.y  + addsrc[(size_t)(2*p+1)*FWSZ + base];
    o[(size_t)(2*p+1)*FWSZ + base + 1] = bv.y + addsrc[(size_t)(2*p+1)*FWSZ + base + 1];
  }
}

extern "C" void kernel_launch(void* const* d_in, const int* in_sizes, int n_in,
                              void* d_out, int out_size){
  const float *x    = (const float*)d_in[0],  *skip = (const float*)d_in[1];
  const float *pqb1 = (const float*)d_in[2],  *pqb2 = (const float*)d_in[3], *sqk = (const float*)d_in[4];
  const float *g1 = (const float*)d_in[5],  *b1 = (const float*)d_in[6];
  const float *wq1 = (const float*)d_in[7], *wk1 = (const float*)d_in[8],
              *wv1 = (const float*)d_in[9], *wo1 = (const float*)d_in[10];
  const float *g2 = (const float*)d_in[11], *b2 = (const float*)d_in[12];
  const float *wq2 = (const float*)d_in[13], *wk2 = (const float*)d_in[14],
              *wv2 = (const float*)d_in[15], *wo2 = (const float*)d_in[16];
  const float *g3 = (const float*)d_in[17], *b3 = (const float*)d_in[18];
  const float *wc1 = (const float*)d_in[19], *wc2 = (const float*)d_in[20];

  float* out = (float*)d_out;
  float* pq1 = out + 8u*FWSZ;
  float* pq2 = pq1 + 64u*QKS;

  float* S = nullptr;
  cudaGetSymbolAddress((void**)&S, g_scratch);
  bf16*  Qh = (bf16*)S;
  bf16*  Ql = (bf16*)(S + (size_t)4u*FWSZ);
  bf16*  Kh = (bf16*)(S + (size_t)8u*FWSZ);
  bf16*  Kl = (bf16*)(S + (size_t)12u*FWSZ);
  bf16*  Vh = (bf16*)(S + (size_t)16u*FWSZ);
  bf16*  Vl = (bf16*)(S + (size_t)20u*FWSZ);
  float* Ap = S + (size_t)24u*FWSZ;
  float* Hp = S + (size_t)32u*FWSZ;   // 24 planes: x | z1 | z2
  float* Tp = S + (size_t)56u*FWSZ;   // 32 planes
  float2* MS = (float2*)(S + (size_t)88u*FWSZ);
  float*  PM = S + (size_t)88u*FWSZ + 24576u;
  float*  PS = PM + 131072u;

  cudaFuncSetAttribute(k_gemm_qk_mma, cudaFuncAttributeMaxDynamicSharedMemorySize, QK_SMEM);
  cudaFuncSetAttribute(k_gemm_av_mma, cudaFuncAttributeMaxDynamicSharedMemorySize, AV_SMEM);

  // ---- attention 1 ----
  k_stats<<<dim3(16,8), 256>>>(x, MS, Hp);                      // stats + copy x->Hp
  k_lnconv<8,3,0,true,3><<<1024, 256>>>(Hp, MS, g1, b1, wq1, wk1, wv1,
                                        Qh, Ql, Kh, Kl, Vh, Vl, nullptr);
  k_gemm_qk_mma<<<dim3(4,4,64), 256, QK_SMEM>>>(Qh, Ql, Kh, Kl, pqb1, sqk, nullptr, pq1, PM, PS);
  k_gemm_av_mma<<<dim3(4,1,64), 256, AV_SMEM>>>(Vh, Vl, pq1, PM, PS, Ap);
  k_lnconv<8,0,1,false,0><<<1024, 256>>>(Ap, nullptr, nullptr, nullptr, wo1, nullptr, nullptr,
                                         nullptr, nullptr, nullptr, nullptr, nullptr, nullptr,
                                         Hp + (size_t)8u*FWSZ);
  // ---- attention 2 ----
  k_stats<<<dim3(16,16), 256>>>(Hp, MS, nullptr);
  k_lnconv<16,1,0,true,1><<<1024, 256>>>(Hp, MS, g2, b2, wq2, nullptr, nullptr,
                                         Qh, Ql, nullptr, nullptr, nullptr, nullptr, nullptr);
  k_lnconv<8,2,0,false,1><<<1024, 256>>>(skip, nullptr, nullptr, nullptr, wk2, wv2, nullptr,
                                         Kh, Kl, Vh, Vl, nullptr, nullptr, nullptr);
  k_gemm_qk_mma<<<dim3(4,4,64), 256, QK_SMEM>>>(Qh, Ql, Kh, Kl, sqk, pqb2, pq1, pq2, PM, PS);
  k_gemm_av_mma<<<dim3(4,1,64), 256, AV_SMEM>>>(Vh, Vl, pq2, PM, PS, Ap);
  k_lnconv<8,0,1,false,0><<<1024, 256>>>(Ap, nullptr, nullptr, nullptr, wo2, nullptr, nullptr,
                                         nullptr, nullptr, nullptr, nullptr, nullptr, nullptr,
                                         Hp + (size_t)16u*FWSZ);
  // ---- conv MLP + residual ----
  k_stats<<<dim3(16,24), 256>>>(Hp, MS, nullptr);
  k_c3ln<<<1024, 256>>>(Hp, MS, g3, b3, wc1, Tp);
  k_c3b<<<1024, 256>>>(Tp, wc2, x, out);
}

// round 14
// speedup vs baseline: 1.0038x; 1.0038x over previous
#include <cuda_runtime.h>
#include <cuda_bf16.h>

#define FWSZ 524288u
#define QKS  262144u
typedef unsigned long long ull;
typedef __nv_bfloat16 bf16;

static __device__ __forceinline__ ull pack2(float lo, float hi){
  ull r; asm("mov.b64 %0,{%1,%2};" : "=l"(r) : "f"(lo), "f"(hi)); return r;
}
static __device__ __forceinline__ void fma2(ull &d, ull a, ull b){
  asm("fma.rn.f32x2 %0,%1,%2,%0;" : "+l"(d) : "l"(a), "l"(b));
}
static __device__ __forceinline__ float2 unpack2(ull v){
  float2 f; asm("mov.b64 {%0,%1},%2;" : "=f"(f.x), "=f"(f.y) : "l"(v)); return f;
}
static __device__ __forceinline__ void mma16816(float* c, const unsigned* a, const unsigned* b){
  asm volatile("mma.sync.aligned.m16n8k16.row.col.f32.bf16.bf16.f32 "
    "{%0,%1,%2,%3},{%4,%5,%6,%7},{%8,%9},{%0,%1,%2,%3};"
    : "+f"(c[0]),"+f"(c[1]),"+f"(c[2]),"+f"(c[3])
    : "r"(a[0]),"r"(a[1]),"r"(a[2]),"r"(a[3]), "r"(b[0]),"r"(b[1]));
}
// fast truncation split: hi = trunc-bf16 pair via PRMT, lo = exact residual, rn-packed
static __device__ __forceinline__ void split2f(float v0, float v1, unsigned &hi, unsigned &lo){
  unsigned u0 = __float_as_uint(v0), u1 = __float_as_uint(v1);
  unsigned h; asm("prmt.b32 %0,%1,%2,0x7632;" : "=r"(h) : "r"(u0), "r"(u1));
  float h0 = __uint_as_float(u0 & 0xFFFF0000u);
  float h1 = __uint_as_float(u1 & 0xFFFF0000u);
  float l0 = v0 - h0, l1 = v1 - h1;
  unsigned lp; asm("cvt.rn.bf16x2.f32 %0,%1,%2;" : "=r"(lp) : "f"(l1), "f"(l0));
  hi = h; lo = lp;
}
static __device__ __forceinline__ void cpa16(unsigned s, const void* g){
  asm volatile("cp.async.cg.shared.global [%0], [%1], 16;\n" :: "r"(s), "l"(g));
}
static __device__ __forceinline__ void cpcommit(){ asm volatile("cp.async.commit_group;\n" ::: "memory"); }
static __device__ __forceinline__ void cpwait0(){ asm volatile("cp.async.wait_group 0;\n" ::: "memory"); }
static __device__ __forceinline__ void cpwait1(){ asm volatile("cp.async.wait_group 1;\n" ::: "memory"); }
static __device__ __forceinline__ unsigned s2u(const void* p){
  return (unsigned)__cvta_generic_to_shared(p);
}

// planes (float units): Qh 0..3, Ql 4..7, Kh 8..11, Kl 12..15 (PAIRED layout), Vh 16..19, Vl 20..23,
// A 24..31, H 32..55, T 56..87; tail MS/PM/PS
__device__ float g_scratch[88u*FWSZ + 300000u];

// ---------------- LN stats over F per (c,w); optional copy-through to cp ----------------
__global__ __launch_bounds__(256) void k_stats(const float* __restrict__ in, float2* __restrict__ ms,
                                               float* __restrict__ cp){
  int c = blockIdx.y, lane = threadIdx.x & 31, fg = threadIdx.x >> 5;
  int w = blockIdx.x*32 + lane;
  const float* base = in + (size_t)c*FWSZ + w;
  float* cpb = cp ? (cp + (size_t)c*FWSZ + w) : nullptr;
  float s = 0.f, s2 = 0.f;
  for (int f = fg; f < 1024; f += 8){
    float v = base[(size_t)f*512u];
    if (cpb) cpb[(size_t)f*512u] = v;
    s += v; s2 += v*v;
  }
  __shared__ float sh[2][8][32];
  sh[0][fg][lane] = s; sh[1][fg][lane] = s2;
  __syncthreads();
  if (fg == 0){
    float S = 0.f, S2 = 0.f;
    #pragma unroll
    for (int r = 0; r < 8; r++){ S += sh[0][r][lane]; S2 += sh[1][r][lane]; }
    float mu  = S*(1.f/1024.f);
    float var = S2*(1.f/1024.f) - mu*mu;
    ms[c*512 + w] = make_float2(mu, rsqrtf(var + 1e-8f));
  }
}

// ---------------- fused (optional-LN) 1x3 conv; NS split-bf16 outputs (+PMASK paired layout) + NP fp32 ----------------
template<int IC, int NS, int NP, bool LN, int PMASK>
__global__ __launch_bounds__(256) void k_lnconv(const float* __restrict__ in, const float2* __restrict__ ms,
    const float* __restrict__ g, const float* __restrict__ b,
    const float* __restrict__ w0, const float* __restrict__ w1, const float* __restrict__ w2,
    bf16* __restrict__ h0, bf16* __restrict__ l0, bf16* __restrict__ h1, bf16* __restrict__ l1,
    bf16* __restrict__ h2, bf16* __restrict__ l2, float* __restrict__ p0)
{
  const int NO = NS + NP;
  __shared__ ull ws[NO*4*IC*3];
  for (int i = threadIdx.x; i < NO*4*IC*3; i += 256){
    int s = i/(4*IC*3), r = i - s*(4*IC*3);
    const float* wsrc = (s==0)? w0 : (s==1)? w1 : w2;
    int p = r/(IC*3), rr = r - p*(IC*3);
    ws[i] = pack2(wsrc[(2*p)*IC*3 + rr], wsrc[(2*p+1)*IC*3 + rr]);
  }
  __syncthreads();
  unsigned t = blockIdx.x*256u + threadIdx.x;
  unsigned base = t*2u;
  int w = base & 511u, f = base >> 9;
  bool w0v = (w > 0), w3v = (w < 510);
  ull acc[NO*4][2];
  #pragma unroll
  for (int p = 0; p < NO*4; p++){ acc[p][0] = 0ull; acc[p][1] = 0ull; }
  #pragma unroll
  for (int ic = 0; ic < IC; ic++){
    const float* ip = in + (size_t)ic*FWSZ + base;
    float v0 = w0v ? ip[-1] : 0.f, v1 = ip[0], v2 = ip[1], v3 = w3v ? ip[2] : 0.f;
    float n0, n1, n2, n3;
    if (LN){
      float gf = g[ic*1024 + f], bf = b[ic*1024 + f];
      const float2* msc = ms + ic*512;
      if (w0v){ float2 m = msc[w-1]; float sc = m.y*gf; n0 = v0*sc + (bf - m.x*sc); } else n0 = 0.f;
      { float2 m = msc[w];   float sc = m.y*gf; n1 = v1*sc + (bf - m.x*sc); }
      { float2 m = msc[w+1]; float sc = m.y*gf; n2 = v2*sc + (bf - m.x*sc); }
      if (w3v){ float2 m = msc[w+2]; float sc = m.y*gf; n3 = v3*sc + (bf - m.x*sc); } else n3 = 0.f;
    } else { n0 = v0; n1 = v1; n2 = v2; n3 = v3; }
    ull b0 = pack2(n0,n0), b1 = pack2(n1,n1), b2 = pack2(n2,n2), b3 = pack2(n3,n3);
    #pragma unroll
    for (int p = 0; p < NO*4; p++){
      const ull* wp = &ws[(p*IC + ic)*3];
      ull q0 = wp[0], q1 = wp[1], q2 = wp[2];
      fma2(acc[p][0], b0, q0); fma2(acc[p][0], b1, q1); fma2(acc[p][0], b2, q2);
      fma2(acc[p][1], b1, q0); fma2(acc[p][1], b2, q1); fma2(acc[p][1], b3, q2);
    }
  }
  int h = f >> 7, dd = f & 127;
  #pragma unroll
  for (int s = 0; s < NS; s++){
    bf16* hp = (s==0)? h0 : (s==1)? h1 : h2;
    bf16* lp = (s==0)? l0 : (s==1)? l1 : l2;
    #pragma unroll
    for (int p = 0; p < 4; p++){
      float2 a = unpack2(acc[s*4+p][0]), c = unpack2(acc[s*4+p][1]);
      if ((PMASK >> s) & 1){
        // paired layout: (dd,w) at (dd>>1)*1024 + 2w + (dd&1); trunc-split stores
        #pragma unroll
        for (int q = 0; q < 2; q++){
          int oc = 2*p + q;
          float u0 = q ? a.y : a.x, u1 = q ? c.y : c.x;
          unsigned b0i = __float_as_uint(u0), b1i = __float_as_uint(u1);
          float h0f = __uint_as_float(b0i & 0xFFFF0000u);
          float h1f = __uint_as_float(b1i & 0xFFFF0000u);
          size_t ib = (size_t)(oc*8 + h)*65536u + (size_t)(dd>>1)*1024u + (unsigned)(dd&1) + 2u*(unsigned)w;
          hp[ib]     = __ushort_as_bfloat16((unsigned short)(b0i >> 16));
          hp[ib + 2] = __ushort_as_bfloat16((unsigned short)(b1i >> 16));
          lp[ib]     = __float2bfloat16(u0 - h0f);
          lp[ib + 2] = __float2bfloat16(u1 - h1f);
        }
      } else {
        unsigned hh, ll;
        split2f(a.x, c.x, hh, ll);
        *(unsigned*)(hp + (size_t)(2*p)*FWSZ + base) = hh;
        *(unsigned*)(lp + (size_t)(2*p)*FWSZ + base) = ll;
        split2f(a.y, c.y, hh, ll);
        *(unsigned*)(hp + (size_t)(2*p+1)*FWSZ + base) = hh;
        *(unsigned*)(lp + (size_t)(2*p+1)*FWSZ + base) = ll;
      }
    }
  }
  if (NP){
    #pragma unroll
    for (int p = 0; p < 4; p++){
      float2 a = unpack2(acc[NS*4+p][0]), c = unpack2(acc[NS*4+p][1]);
      p0[(size_t)(2*p)*FWSZ   + base]     = a.x;
      p0[(size_t)(2*p)*FWSZ   + base + 1] = c.x;
      p0[(size_t)(2*p+1)*FWSZ + base]     = a.y;
      p0[(size_t)(2*p+1)*FWSZ + base + 1] = c.y;
    }
  }
}

// ---------------- QK^T split-bf16 mma, cp.async double-buffered, PAIRED operand layout ----------------
// Qh/Ql/Kh/Kl planes: [z][dd2(64)][w(512)][2] bf16. grid (4 kw,4 qw,64 z), 256 thr.
#define QK_TILE 4352            // 16 rows * 272 bf16 per tensor per buffer
#define QK_SMEM (2*4*QK_TILE*2) // 69632 bytes
__global__ __launch_bounds__(256,2) void k_gemm_qk_mma(
    const bf16* __restrict__ Qh, const bf16* __restrict__ Ql,
    const bf16* __restrict__ Kh, const bf16* __restrict__ Kl,
    const float* __restrict__ b1p, const float* __restrict__ b2p, const float* __restrict__ b3p,
    float* __restrict__ o, float* __restrict__ pmax, float* __restrict__ psum)
{
  extern __shared__ bf16 dynqk[];
  __shared__ float red[512];
  __shared__ float mrow[128];
  int z = blockIdx.z, qw0 = blockIdx.y*128, kw0 = blockIdx.x*128, bx = blockIdx.x;
  int tid = threadIdx.x, lane = tid & 31, wid = tid >> 5;
  int wy = wid >> 2, wx = wid & 3;
  int m0 = wy*64, n0 = wx*32;
  int g = lane >> 2, t4 = lane & 3;
  const bf16* bQh = Qh + (size_t)z*65536u + 2u*qw0;
  const bf16* bQl = Ql + (size_t)z*65536u + 2u*qw0;
  const bf16* bKh = Kh + (size_t)z*65536u + 2u*kw0;
  const bf16* bKl = Kl + (size_t)z*65536u + 2u*kw0;

  auto fill = [&](int kb, int buf){
    int d20 = kb*16;
    bf16* sb = dynqk + buf*(4*QK_TILE);
    #pragma unroll
    for (int it = 0; it < 8; it++){
      int c = it*256 + tid;
      int tt = c >> 9, rem = c & 511, row = rem >> 5, ch = rem & 31;
      const bf16* gp = ((tt==0)?bQh:(tt==1)?bQl:(tt==2)?bKh:bKl)
                       + (size_t)(d20+row)*1024u + ch*8;
      cpa16(s2u(sb + tt*QK_TILE + row*272 + ch*8), gp);
    }
    cpcommit();
  };

  float acc[4][4][4];
  #pragma unroll
  for (int mt = 0; mt < 4; mt++)
    #pragma unroll
    for (int nt = 0; nt < 4; nt++)
      #pragma unroll
      for (int i = 0; i < 4; i++) acc[mt][nt][i] = 0.f;

  fill(0, 0);
  for (int kb = 0; kb < 4; kb++){
    if (kb < 3){ fill(kb+1, (kb+1)&1); cpwait1(); } else cpwait0();
    __syncthreads();
    const unsigned* wT  = (const unsigned*)(dynqk + (kb&1)*(4*QK_TILE));
    const unsigned* wQh = wT;
    const unsigned* wQl = wT + 2176;
    const unsigned* wKh = wT + 4352;
    const unsigned* wKl = wT + 6528;
    #pragma unroll
    for (int ks = 0; ks < 2; ks++){
      int rb0 = (ks*8 + t4)*136, rb4 = rb0 + 4*136;
      unsigned bh[4][2], bl[4][2];
      #pragma unroll
      for (int nt = 0; nt < 4; nt++){
        int n = n0 + nt*8 + g;
        bh[nt][0] = wKh[rb0 + n]; bh[nt][1] = wKh[rb4 + n];
        bl[nt][0] = wKl[rb0 + n]; bl[nt][1] = wKl[rb4 + n];
      }
      #pragma unroll
      for (int mt = 0; mt < 4; mt++){
        int m = m0 + mt*16 + g;
        unsigned ah[4], al[4];
        ah[0] = wQh[rb0 + m]; ah[1] = wQh[rb0 + m + 8];
        ah[2] = wQh[rb4 + m]; ah[3] = wQh[rb4 + m + 8];
        al[0] = wQl[rb0 + m]; al[1] = wQl[rb0 + m + 8];
        al[2] = wQl[rb4 + m]; al[3] = wQl[rb4 + m + 8];
        #pragma unroll
        for (int nt = 0; nt < 4; nt++){
          mma16816(acc[mt][nt], ah, bh[nt]);
          mma16816(acc[mt][nt], ah, bl[nt]);
          mma16816(acc[mt][nt], al, bh[nt]);
        }
      }
    }
    __syncthreads();
  }

  const float sc = 0.08838834764831845f;   // 1/sqrt(128)
  #pragma unroll
  for (int mt = 0; mt < 4; mt++){
    #pragma unroll
    for (int half = 0; half < 2; half++){
      int lrow = m0 + mt*16 + g + half*8;
      size_t rowb = (size_t)z*QKS + (size_t)(qw0 + lrow)*512u;
      #pragma unroll
      for (int nt = 0; nt < 4; nt++){
        size_t ix = rowb + kw0 + n0 + nt*8 + 2*t4;
        float v0 = acc[mt][nt][half*2+0]*sc, v1 = acc[mt][nt][half*2+1]*sc;
        float2 c1 = *(const float2*)(b1p + ix), c2 = *(const float2*)(b2p + ix);
        v0 += c1.x + c2.x; v1 += c1.y + c2.y;
        if (b3p){ float2 c3 = *(const float2*)(b3p + ix); v0 += c3.x; v1 += c3.y; }
        *(float2*)(o + ix) = make_float2(v0, v1);
        acc[mt][nt][half*2+0] = v0; acc[mt][nt][half*2+1] = v1;
      }
    }
  }
  #pragma unroll
  for (int mt = 0; mt < 4; mt++){
    #pragma unroll
    for (int half = 0; half < 2; half++){
      float m = -3.4e38f;
      #pragma unroll
      for (int nt = 0; nt < 4; nt++){
        m = fmaxf(m, acc[mt][nt][half*2+0]); m = fmaxf(m, acc[mt][nt][half*2+1]);
      }
      m = fmaxf(m, __shfl_xor_sync(0xffffffffu, m, 1));
      m = fmaxf(m, __shfl_xor_sync(0xffffffffu, m, 2));
      int lrow = m0 + mt*16 + g + half*8;
      if (t4 == 0) red[lrow*4 + wx] = m;
    }
  }
  __syncthreads();
  if (tid < 128)
    mrow[tid] = fmaxf(fmaxf(red[tid*4], red[tid*4+1]), fmaxf(red[tid*4+2], red[tid*4+3]));
  __syncthreads();
  #pragma unroll
  for (int mt = 0; mt < 4; mt++){
    #pragma unroll
    for (int half = 0; half < 2; half++){
      int lrow = m0 + mt*16 + g + half*8;
      float M = mrow[lrow];
      float s = 0.f;
      #pragma unroll
      for (int nt = 0; nt < 4; nt++)
        s += __expf(acc[mt][nt][half*2+0] - M) + __expf(acc[mt][nt][half*2+1] - M);
      s += __shfl_xor_sync(0xffffffffu, s, 1);
      s += __shfl_xor_sync(0xffffffffu, s, 2);
      if (t4 == 0) red[lrow*4 + wx] = s;
    }
  }
  __syncthreads();
  if (tid < 128){
    float S = red[tid*4] + red[tid*4+1] + red[tid*4+2] + red[tid*4+3];
    size_t pi = ((size_t)z*512u + qw0 + tid)*4u + bx;
    pmax[pi] = mrow[tid]; psum[pi] = S;
  }
}

// ---------------- AV split-bf16 mma, cp.async double-buffered, fused softmax ----------------
// Vh/Vl planes [z][dd][kw] bf16; P fp32 [z][qw][kw]. grid (4,1,64), 256 thr.
#define AV_VT 10240    // 128*40 bf16 bytes
#define AV_PT 18432    // 128*36 fp32 bytes
#define AV_BUF (2*AV_VT + AV_PT)   // 38912
#define AV_SMEM (2*AV_BUF)         // 77824
__global__ __launch_bounds__(256,2) void k_gemm_av_mma(
    const bf16* __restrict__ Vh, const bf16* __restrict__ Vl, const float* __restrict__ pq,
    const float* __restrict__ pmax, const float* __restrict__ psum, float* __restrict__ A)
{
  extern __shared__ char dynav[];
  __shared__ float mxs[128], ivs[128];
  int z = blockIdx.z, qw0 = blockIdx.x*128;
  int tid = threadIdx.x, lane = tid & 31, wid = tid >> 5;
  int wy = wid >> 2, wx = wid & 3;
  int m0 = wy*64, n0 = wx*32;
  int g = lane >> 2, t4 = lane & 3;
  const bf16* bVh = Vh + (size_t)z*65536u;
  const bf16* bVl = Vl + (size_t)z*65536u;
  const float* bP = pq + (size_t)z*QKS;
  if (tid < 128){
    size_t pi = ((size_t)z*512u + qw0 + tid)*4u;
    float m0v = pmax[pi], m1 = pmax[pi+1], m2 = pmax[pi+2], m3 = pmax[pi+3];
    float m = fmaxf(fmaxf(m0v,m1), fmaxf(m2,m3));
    float s = psum[pi]*__expf(m0v-m) + psum[pi+1]*__expf(m1-m)
            + psum[pi+2]*__expf(m2-m) + psum[pi+3]*__expf(m3-m);
    mxs[tid] = m; ivs[tid] = 1.f/s;
  }

  auto fill = [&](int kc, int buf){
    int k0 = kc*32;
    char* base = dynav + buf*AV_BUF;
    #pragma unroll
    for (int it = 0; it < 8; it++){
      int c = it*256 + tid;
      if (c < 1024){
        int tt = c >> 9, rem = c & 511, row = rem >> 2, col = rem & 3;
        const bf16* gp = (tt ? bVl : bVh) + (size_t)row*512u + k0 + col*8;
        cpa16(s2u(base + tt*AV_VT + (row*40 + col*8)*2), gp);
      } else {
        int rem = c - 1024, row = rem >> 3, col = rem & 7;
        const float* gp = bP + (size_t)(qw0+row)*512u + k0 + col*4;
        cpa16(s2u(base + 2*AV_VT + (row*36 + col*4)*4), gp);
      }
    }
    cpcommit();
  };

  float acc[4][4][4];
  #pragma unroll
  for (int mt = 0; mt < 4; mt++)
    #pragma unroll
    for (int nt = 0; nt < 4; nt++)
      #pragma unroll
      for (int i = 0; i < 4; i++) acc[mt][nt][i] = 0.f;

  fill(0, 0);
  for (int kc = 0; kc < 16; kc++){
    if (kc < 15){ fill(kc+1, (kc+1)&1); cpwait1(); } else cpwait0();
    __syncthreads();
    char* cb = dynav + (kc&1)*AV_BUF;
    const bf16* sVh_ = (const bf16*)cb;
    const bf16* sVl_ = (const bf16*)(cb + AV_VT);
    const float* sP_ = (const float*)(cb + 2*AV_VT);
    #pragma unroll
    for (int ks = 0; ks < 2; ks++){
      int kk = ks*16 + 2*t4;
      unsigned bh[4][2], bl[4][2];
      #pragma unroll
      for (int nt = 0; nt < 4; nt++){
        int row = n0 + nt*8 + g;
        float mrw = mxs[row];
        const float* pb = sP_ + row*36 + kk;
        float2 v0 = *(const float2*)pb;
        float2 v1 = *(const float2*)(pb + 8);
        float e0 = __expf(v0.x-mrw), e1 = __expf(v0.y-mrw);
        float e2 = __expf(v1.x-mrw), e3 = __expf(v1.y-mrw);
        split2f(e0, e1, bh[nt][0], bl[nt][0]);
        split2f(e2, e3, bh[nt][1], bl[nt][1]);
      }
      #pragma unroll
      for (int mt = 0; mt < 4; mt++){
        int row = m0 + mt*16 + g;
        unsigned ah[4], al[4];
        ah[0] = *(const unsigned*)(sVh_ + row*40 + kk);
        ah[1] = *(const unsigned*)(sVh_ + (row+8)*40 + kk);
        ah[2] = *(const unsigned*)(sVh_ + row*40 + kk+8);
        ah[3] = *(const unsigned*)(sVh_ + (row+8)*40 + kk+8);
        al[0] = *(const unsigned*)(sVl_ + row*40 + kk);
        al[1] = *(const unsigned*)(sVl_ + (row+8)*40 + kk);
        al[2] = *(const unsigned*)(sVl_ + row*40 + kk+8);
        al[3] = *(const unsigned*)(sVl_ + (row+8)*40 + kk+8);
        #pragma unroll
        for (int nt = 0; nt < 4; nt++){
          mma16816(acc[mt][nt], ah, bh[nt]);
          mma16816(acc[mt][nt], ah, bl[nt]);
          mma16816(acc[mt][nt], al, bh[nt]);
        }
      }
    }
    __syncthreads();
  }
  #pragma unroll
  for (int mt = 0; mt < 4; mt++){
    #pragma unroll
    for (int half = 0; half < 2; half++){
      int row = m0 + mt*16 + g + half*8;
      size_t rowb = (size_t)z*65536u + (size_t)row*512u + qw0;
      #pragma unroll
      for (int nt = 0; nt < 4; nt++){
        int col = n0 + nt*8 + 2*t4;
        float iv0 = ivs[col], iv1 = ivs[col+1];
        *(float2*)(A + rowb + col) =
            make_float2(acc[mt][nt][half*2+0]*iv0, acc[mt][nt][half*2+1]*iv1);
      }
    }
  }
}

// ---------------- 3x3 conv with fused LN (24ch -> 32ch), SquaredReLU ----------------
__global__ __launch_bounds__(256) void k_c3ln(const float* __restrict__ in, const float2* __restrict__ ms,
    const float* __restrict__ g, const float* __restrict__ b, const float* __restrict__ wgt,
    float* __restrict__ o)
{
  __shared__ ull ws[16*24*9];
  for (int i = threadIdx.x; i < 16*24*9; i += 256){
    int p = i/216, r = i - p*216;
    ws[i] = pack2(wgt[(2*p)*216 + r], wgt[(2*p+1)*216 + r]);
  }
  __syncthreads();
  unsigned t = blockIdx.x*256u + threadIdx.x;
  unsigned base = t*2u;
  int w = base & 511u, f = base >> 9;
  bool r0v = (f > 0), r2v = (f < 1023), w0v = (w > 0), w3v = (w < 510);
  ull acc[16][2];
  #pragma unroll
  for (int p = 0; p < 16; p++){ acc[p][0] = 0ull; acc[p][1] = 0ull; }
  #pragma unroll 2
  for (int ic = 0; ic < 24; ic++){
    const float* ip = in + (size_t)ic*FWSZ + base;
    const float2* msc = ms + ic*512;
    float gm1 = r0v ? g[ic*1024+f-1] : 0.f, bm1 = r0v ? b[ic*1024+f-1] : 0.f;
    float gc  = g[ic*1024+f],               bc  = b[ic*1024+f];
    float gp1 = r2v ? g[ic*1024+f+1] : 0.f, bp1 = r2v ? b[ic*1024+f+1] : 0.f;
    float2 m0 = w0v ? msc[w-1] : make_float2(0.f,1.f);
    float2 m1 = msc[w], m2 = msc[w+1];
    float2 m3 = w3v ? msc[w+2] : make_float2(0.f,1.f);
    float u[3][4];
    {
      const float* rp = ip - 512;
      u[0][0] = (r0v&&w0v)? rp[-1]:0.f; u[0][1] = r0v? rp[0]:0.f; u[0][2] = r0v? rp[1]:0.f; u[0][3] = (r0v&&w3v)? rp[2]:0.f;
      u[1][0] = w0v? ip[-1]:0.f;        u[1][1] = ip[0];          u[1][2] = ip[1];          u[1][3] = w3v? ip[2]:0.f;
      const float* rq = ip + 512;
      u[2][0] = (r2v&&w0v)? rq[-1]:0.f; u[2][1] = r2v? rq[0]:0.f; u[2][2] = r2v? rq[1]:0.f; u[2][3] = (r2v&&w3v)? rq[2]:0.f;
    }
    auto nrm = [] (float v, float2 m, float gg, float bb, bool valid)->float{
      float sc = m.y*gg; return valid ? (v*sc + (bb - m.x*sc)) : 0.f; };
    u[0][0] = nrm(u[0][0], m0, gm1, bm1, r0v&&w0v);
    u[0][1] = nrm(u[0][1], m1, gm1, bm1, r0v);
    u[0][2] = nrm(u[0][2], m2, gm1, bm1, r0v);
    u[0][3] = nrm(u[0][3], m3, gm1, bm1, r0v&&w3v);
    u[1][0] = nrm(u[1][0], m0, gc,  bc,  w0v);
    u[1][1] = nrm(u[1][1], m1, gc,  bc,  true);
    u[1][2] = nrm(u[1][2], m2, gc,  bc,  true);
    u[1][3] = nrm(u[1][3], m3, gc,  bc,  w3v);
    u[2][0] = nrm(u[2][0], m0, gp1, bp1, r2v&&w0v);
    u[2][1] = nrm(u[2][1], m1, gp1, bp1, r2v);
    u[2][2] = nrm(u[2][2], m2, gp1, bp1, r2v);
    u[2][3] = nrm(u[2][3], m3, gp1, bp1, r2v&&w3v);
    #pragma unroll
    for (int k = 0; k < 9; k++){
      int ky = k/3, kx = k - ky*3;
      ull b0 = pack2(u[ky][kx],   u[ky][kx]);
      ull b1 = pack2(u[ky][kx+1], u[ky][kx+1]);
      #pragma unroll
      for (int p = 0; p < 16; p++){
        ull wv = ws[(p*24 + ic)*9 + k];
        fma2(acc[p][0], b0, wv); fma2(acc[p][1], b1, wv);
      }
    }
  }
  #pragma unroll
  for (int p = 0; p < 16; p++){
    float2 a = unpack2(acc[p][0]), bv = unpack2(acc[p][1]);
    float o00 = fmaxf(a.x, 0.f);  o00 *= o00;
    float o10 = fmaxf(a.y, 0.f);  o10 *= o10;
    float o01 = fmaxf(bv.x, 0.f); o01 *= o01;
    float o11 = fmaxf(bv.y, 0.f); o11 *= o11;
    o[(size_t)(2*p)*FWSZ   + base]     = o00;
    o[(size_t)(2*p)*FWSZ   + base + 1] = o01;
    o[(size_t)(2*p+1)*FWSZ + base]     = o10;
    o[(size_t)(2*p+1)*FWSZ + base + 1] = o11;
  }
}

// ---------------- plain 3x3 conv (32ch -> 8ch) + residual add ----------------
__global__ __launch_bounds__(256) void k_c3b(const float* __restrict__ in, const float* __restrict__ wgt,
    const float* __restrict__ addsrc, float* __restrict__ o)
{
  __shared__ ull ws[4*32*9];
  for (int i = threadIdx.x; i < 4*32*9; i += 256){
    int p = i/288, r = i - p*288;
    ws[i] = pack2(wgt[(2*p)*288 + r], wgt[(2*p+1)*288 + r]);
  }
  __syncthreads();
  unsigned t = blockIdx.x*256u + threadIdx.x;
  unsigned base = t*2u;
  int w = base & 511u, f = base >> 9;
  bool r0v = (f > 0), r2v = (f < 1023), w0v = (w > 0), w3v = (w < 510);
  ull acc[4][2];
  #pragma unroll
  for (int p = 0; p < 4; p++){ acc[p][0] = 0ull; acc[p][1] = 0ull; }
  #pragma unroll 4
  for (int ic = 0; ic < 32; ic++){
    const float* ip = in + (size_t)ic*FWSZ + base;
    float u[3][4];
    {
      const float* rp = ip - 512;
      u[0][0] = (r0v&&w0v)? rp[-1]:0.f; u[0][1] = r0v? rp[0]:0.f; u[0][2] = r0v? rp[1]:0.f; u[0][3] = (r0v&&w3v)? rp[2]:0.f;
      u[1][0] = w0v? ip[-1]:0.f;        u[1][1] = ip[0];          u[1][2] = ip[1];          u[1][3] = w3v? ip[2]:0.f;
      const float* rq = ip + 512;
      u[2][0] = (r2v&&w0v)? rq[-1]:0.f; u[2][1] = r2v? rq[0]:0.f; u[2][2] = r2v? rq[1]:0.f; u[2][3] = (r2v&&w3v)? rq[2]:0.f;
    }
    #pragma unroll
    for (int k = 0; k < 9; k++){
      int ky = k/3, kx = k - ky*3;
      ull b0 = pack2(u[ky][kx],   u[ky][kx]);
      ull b1 = pack2(u[ky][kx+1], u[ky][kx+1]);
      #pragma unroll
      for (int p = 0; p < 4; p++){
        ull wv = ws[(p*32 + ic)*9 + k];
        fma2(acc[p][0], b0, wv); fma2(acc[p][1], b1, wv);
      }
    }
  }
  #pragma unroll
  for (int p = 0; p < 4; p++){
    float2 a = unpack2(acc[p][0]), bv = unpack2(acc[p][1]);
    o[(size_t)(2*p)*FWSZ   + base]     = a.x  + addsrc[(size_t)(2*p)*FWSZ + base];
    o[(size_t)(2*p)*FWSZ   + base + 1] = bv.x + addsrc[(size_t)(2*p)*FWSZ + base + 1];
    o[(size_t)(2*p+1)*FWSZ + base]     = a.y  + addsrc[(size_t)(2*p+1)*FWSZ + base];
    o[(size_t)(2*p+1)*FWSZ + base + 1] = bv.y + addsrc[(size_t)(2*p+1)*FWSZ + base + 1];
  }
}

extern "C" void kernel_launch(void* const* d_in, const int* in_sizes, int n_in,
                              void* d_out, int out_size){
  const float *x    = (const float*)d_in[0],  *skip = (const float*)d_in[1];
  const float *pqb1 = (const float*)d_in[2],  *pqb2 = (const float*)d_in[3], *sqk = (const float*)d_in[4];
  const float *g1 = (const float*)d_in[5],  *b1 = (const float*)d_in[6];
  const float *wq1 = (const float*)d_in[7], *wk1 = (const float*)d_in[8],
              *wv1 = (const float*)d_in[9], *wo1 = (const float*)d_in[10];
  const float *g2 = (const float*)d_in[11], *b2 = (const float*)d_in[12];
  const float *wq2 = (const float*)d_in[13], *wk2 = (const float*)d_in[14],
              *wv2 = (const float*)d_in[15], *wo2 = (const float*)d_in[16];
  const float *g3 = (const float*)d_in[17], *b3 = (const float*)d_in[18];
  const float *wc1 = (const float*)d_in[19], *wc2 = (const float*)d_in[20];

  float* out = (float*)d_out;
  float* pq1 = out + 8u*FWSZ;
  float* pq2 = pq1 + 64u*QKS;

  float* S = nullptr;
  cudaGetSymbolAddress((void**)&S, g_scratch);
  bf16*  Qh = (bf16*)S;
  bf16*  Ql = (bf16*)(S + (size_t)4u*FWSZ);
  bf16*  Kh = (bf16*)(S + (size_t)8u*FWSZ);
  bf16*  Kl = (bf16*)(S + (size_t)12u*FWSZ);
  bf16*  Vh = (bf16*)(S + (size_t)16u*FWSZ);
  bf16*  Vl = (bf16*)(S + (size_t)20u*FWSZ);
  float* Ap = S + (size_t)24u*FWSZ;
  float* Hp = S + (size_t)32u*FWSZ;   // 24 planes: x | z1 | z2
  float* Tp = S + (size_t)56u*FWSZ;   // 32 planes
  float2* MS = (float2*)(S + (size_t)88u*FWSZ);
  float*  PM = S + (size_t)88u*FWSZ + 24576u;
  float*  PS = PM + 131072u;

  cudaFuncSetAttribute(k_gemm_qk_mma, cudaFuncAttributeMaxDynamicSharedMemorySize, QK_SMEM);
  cudaFuncSetAttribute(k_gemm_av_mma, cudaFuncAttributeMaxDynamicSharedMemorySize, AV_SMEM);

  // ---- attention 1 ----
  k_stats<<<dim3(16,8), 256>>>(x, MS, Hp);                      // stats + copy x->Hp
  k_lnconv<8,3,0,true,3><<<1024, 256>>>(Hp, MS, g1, b1, wq1, wk1, wv1,
                                        Qh, Ql, Kh, Kl, Vh, Vl, nullptr);
  k_gemm_qk_mma<<<dim3(4,4,64), 256, QK_SMEM>>>(Qh, Ql, Kh, Kl, pqb1, sqk, nullptr, pq1, PM, PS);
  k_gemm_av_mma<<<dim3(4,1,64), 256, AV_SMEM>>>(Vh, Vl, pq1, PM, PS, Ap);
  k_lnconv<8,0,1,false,0><<<1024, 256>>>(Ap, nullptr, nullptr, nullptr, wo1, nullptr, nullptr,
                                         nullptr, nullptr, nullptr, nullptr, nullptr, nullptr,
                                         Hp + (size_t)8u*FWSZ);
  // ---- attention 2 ----
  k_stats<<<dim3(16,16), 256>>>(Hp, MS, nullptr);
  k_lnconv<16,1,0,true,1><<<1024, 256>>>(Hp, MS, g2, b2, wq2, nullptr, nullptr,
                                         Qh, Ql, nullptr, nullptr, nullptr, nullptr, nullptr);
  k_lnconv<8,2,0,false,1><<<1024, 256>>>(skip, nullptr, nullptr, nullptr, wk2, wv2, nullptr,
                                         Kh, Kl, Vh, Vl, nullptr, nullptr, nullptr);
  k_gemm_qk_mma<<<dim3(4,4,64), 256, QK_SMEM>>>(Qh, Ql, Kh, Kl, sqk, pqb2, pq1, pq2, PM, PS);
  k_gemm_av_mma<<<dim3(4,1,64), 256, AV_SMEM>>>(Vh, Vl, pq2, PM, PS, Ap);
  k_lnconv<8,0,1,false,0><<<1024, 256>>>(Ap, nullptr, nullptr, nullptr, wo2, nullptr, nullptr,
                                         nullptr, nullptr, nullptr, nullptr, nullptr, nullptr,
                                         Hp + (size_t)16u*FWSZ);
  // ---- conv MLP + residual ----
  k_stats<<<dim3(16,24), 256>>>(Hp, MS, nullptr);
  k_c3ln<<<1024, 256>>>(Hp, MS, g3, b3, wc1, Tp);
  k_c3b<<<1024, 256>>>(Tp, wc2, x, out);
}